// round 5
// baseline (speedup 1.0000x reference)
#include <cuda_runtime.h>
#include <cstdint>

// Triangle_39719857553609:
//   in : decompFE [32768, 2016] f32 (flat strict-lower-triangle, tril(-1) order)
//   out: [32768, 64, 64] f32, symmetric, zero diagonal.
//
// R5: persistent double-buffered bulk pipeline. 592 CTAs (148 SM x 4), each
// grid-strides over ~55 matrices:
//   prefetch row i+1 (cp.async.bulk + mbarrier) || build matrix i in smem
//   || bulk store matrix i (one outstanding store allowed, wait_group.read 1).
// Loads and stores are simultaneously in flight at all times per CTA.

#define NC2        2016
#define ROW_BYTES  (NC2 * 4)            // 8064
#define N_ATOMS    64
#define MAT        (N_ATOMS * N_ATOMS)  // 4096
#define MAT_BYTES  (MAT * 4)            // 16384
#define THREADS    256
#define BATCH      32768
#define GRID       (148 * 4)            // 592 persistent CTAs

__device__ __forceinline__ uint32_t smem_u32(const void* p) {
    uint32_t a;
    asm("{ .reg .u64 t; cvta.to.shared.u64 t, %1; cvt.u32.u64 %0, t; }"
        : "=r"(a) : "l"(p));
    return a;
}

__device__ __forceinline__ void mbar_wait(uint32_t mbar, int parity) {
    asm volatile(
        "{\n\t"
        ".reg .pred p;\n\t"
        "W_%=:\n\t"
        "mbarrier.try_wait.parity.shared.b64 p, [%0], %1;\n\t"
        "@!p bra W_%=;\n\t"
        "}"
        :: "r"(mbar), "r"(parity) : "memory");
}

__global__ __launch_bounds__(THREADS) void triangle_kernel(
    const float* __restrict__ in, float* __restrict__ out)
{
    __shared__ alignas(16) float s_row[2][NC2];   // 16128 B
    __shared__ alignas(16) float s_mat[2][MAT];   // 32768 B
    __shared__ alignas(8)  uint64_t s_mbar[2];

    const int tid = threadIdx.x;
    const uint32_t mb[2] = { smem_u32(&s_mbar[0]), smem_u32(&s_mbar[1]) };

    if (tid == 0) {
        asm volatile("mbarrier.init.shared.b64 [%0], 1;" :: "r"(mb[0]) : "memory");
        asm volatile("mbarrier.init.shared.b64 [%0], 1;" :: "r"(mb[1]) : "memory");
    }
    __syncthreads();

    const size_t b0     = blockIdx.x;
    const size_t stride = GRID;

    // ---- prologue: load first row into slot 0 ----
    if (tid == 0 && b0 < BATCH) {
        asm volatile("mbarrier.arrive.expect_tx.shared.b64 _, [%0], %1;"
                     :: "r"(mb[0]), "r"((uint32_t)ROW_BYTES) : "memory");
        asm volatile(
            "cp.async.bulk.shared::cta.global.mbarrier::complete_tx::bytes "
            "[%0], [%1], %2, [%3];"
            :: "r"(smem_u32(s_row[0])), "l"(in + b0 * NC2),
               "r"((uint32_t)ROW_BYTES), "r"(mb[0]) : "memory");
    }

    int ph0 = 0, ph1 = 0;
    int s = 0;
    for (size_t b = b0; b < BATCH; b += stride, s ^= 1) {
        const size_t bn = b + stride;

        // prefetch next row into the other slot
        if (tid == 0 && bn < BATCH) {
            asm volatile("mbarrier.arrive.expect_tx.shared.b64 _, [%0], %1;"
                         :: "r"(mb[s ^ 1]), "r"((uint32_t)ROW_BYTES) : "memory");
            asm volatile(
                "cp.async.bulk.shared::cta.global.mbarrier::complete_tx::bytes "
                "[%0], [%1], %2, [%3];"
                :: "r"(smem_u32(s_row[s ^ 1])), "l"(in + bn * NC2),
                   "r"((uint32_t)ROW_BYTES), "r"(mb[s ^ 1]) : "memory");
        }

        // wait for row b
        if (s == 0) { mbar_wait(mb[0], ph0); ph0 ^= 1; }
        else        { mbar_wait(mb[1], ph1); ph1 ^= 1; }

        // matbuf[s] must be drained by the store from two iterations ago
        // (allow the most recent store to stay outstanding)
        if (tid == 0)
            asm volatile("cp.async.bulk.wait_group.read 1;" ::: "memory");
        __syncthreads();

        // ---- build symmetric matrix b into s_mat[s] ----
        const float* __restrict__ r = s_row[s];
        float4* m4 = reinterpret_cast<float4*>(s_mat[s]);
        #pragma unroll
        for (int q = 0; q < MAT / 4 / THREADS; q++) {
            const int e4 = tid + q * THREADS;      // float4 index in matrix
            const int i  = e4 >> 4;                // row (16 float4/row)
            const int j0 = (e4 & 15) << 2;
            const int tri_i = (i * (i - 1)) >> 1;

            float4 v;
            float* vp = reinterpret_cast<float*>(&v);
            #pragma unroll
            for (int mI = 0; mI < 4; mI++) {
                const int j = j0 + mI;
                float val;
                if (j < i)       val = r[tri_i + j];                 // lower
                else if (j > i)  val = r[((j * (j - 1)) >> 1) + i];  // upper
                else             val = 0.0f;                         // diag
                vp[mI] = val;
            }
            m4[e4] = v;
        }
        __syncthreads();

        // ---- issue async bulk store of matrix b ----
        if (tid == 0) {
            asm volatile("fence.proxy.async.shared::cta;" ::: "memory");
            asm volatile(
                "cp.async.bulk.global.shared::cta.bulk_group [%0], [%1], %2;"
                :: "l"(out + b * MAT), "r"(smem_u32(s_mat[s])),
                   "r"((uint32_t)MAT_BYTES) : "memory");
            asm volatile("cp.async.bulk.commit_group;" ::: "memory");
        }
    }

    // drain outstanding stores before exit
    if (tid == 0)
        asm volatile("cp.async.bulk.wait_group 0;" ::: "memory");
}

extern "C" void kernel_launch(void* const* d_in, const int* in_sizes, int n_in,
                              void* d_out, int out_size)
{
    const float* decompFE = (const float*)d_in[0];
    float* out = (float*)d_out;

    triangle_kernel<<<GRID, THREADS>>>(decompFE, out);
}

// round 6
// speedup vs baseline: 1.1056x; 1.1056x over previous
#include <cuda_runtime.h>
#include <cstdint>

// Triangle_39719857553609:
//   in : decompFE [32768, 2016] f32 (flat strict-lower-triangle, tril(-1) order)
//   out: [32768, 64, 64] f32, symmetric, zero diagonal.
//
// R6: maximize independent resident streams. One CTA per matrix, 128 threads,
// 8.1 KB smem -> 16 CTAs/SM (full 64-warp occupancy, 2x R1/R3 stream count).
// Load: single cp.async.bulk (8064 B) + mbarrier. Store: direct float4 STGs
// (R4/R5 proved burst shape doesn't matter; stream count does).

#define NC2        2016
#define ROW_BYTES  (NC2 * 4)            // 8064
#define N_ATOMS    64
#define MAT        (N_ATOMS * N_ATOMS)  // 4096
#define THREADS    128

__device__ __forceinline__ uint32_t smem_u32(const void* p) {
    uint32_t a;
    asm("{ .reg .u64 t; cvta.to.shared.u64 t, %1; cvt.u32.u64 %0, t; }"
        : "=r"(a) : "l"(p));
    return a;
}

__global__ __launch_bounds__(THREADS) void triangle_kernel(
    const float* __restrict__ in, float* __restrict__ out)
{
    __shared__ alignas(16) float s_row[NC2];
    __shared__ alignas(8)  uint64_t s_mbar;

    const int tid = threadIdx.x;
    const size_t b = blockIdx.x;

    const uint32_t mbar_a = smem_u32(&s_mbar);

    if (tid == 0) {
        asm volatile("mbarrier.init.shared.b64 [%0], 1;" :: "r"(mbar_a) : "memory");
        // fence not needed before the arrive below: same thread, program order,
        // but the bulk-copy engine needs init visible -> use proxy fence.
        asm volatile("fence.proxy.async.shared::cta;" ::: "memory");
        asm volatile("mbarrier.arrive.expect_tx.shared.b64 _, [%0], %1;"
                     :: "r"(mbar_a), "r"((uint32_t)ROW_BYTES) : "memory");
        asm volatile(
            "cp.async.bulk.shared::cta.global.mbarrier::complete_tx::bytes "
            "[%0], [%1], %2, [%3];"
            :: "r"(smem_u32(s_row)), "l"(in + b * NC2),
               "r"((uint32_t)ROW_BYTES), "r"(mbar_a) : "memory");
    }
    __syncthreads();   // make mbarrier init visible to all threads before wait

    // all threads wait for the row (parity 0)
    asm volatile(
        "{\n\t"
        ".reg .pred p;\n\t"
        "W_%=:\n\t"
        "mbarrier.try_wait.parity.shared.b64 p, [%0], 0;\n\t"
        "@!p bra W_%=;\n\t"
        "}"
        :: "r"(mbar_a) : "memory");

    // ---- emit 4096 outputs: 1024 float4 stores, 8 per thread ----
    float4* out4 = reinterpret_cast<float4*>(out + b * MAT);

    #pragma unroll
    for (int q = 0; q < MAT / 4 / THREADS; q++) {
        const int e4 = tid + q * THREADS;        // float4 index within matrix
        const int i  = e4 >> 4;                  // row (16 float4 per row)
        const int j0 = (e4 & 15) << 2;           // first col of this float4
        const int tri_i = (i * (i - 1)) >> 1;

        float4 v;
        float* vp = reinterpret_cast<float*>(&v);
        #pragma unroll
        for (int m = 0; m < 4; m++) {
            const int j = j0 + m;
            float val;
            if (j < i)       val = s_row[tri_i + j];                 // lower
            else if (j > i)  val = s_row[((j * (j - 1)) >> 1) + i];  // upper
            else             val = 0.0f;                             // diag
            vp[m] = val;
        }
        out4[e4] = v;
    }
}

extern "C" void kernel_launch(void* const* d_in, const int* in_sizes, int n_in,
                              void* d_out, int out_size)
{
    const float* decompFE = (const float*)d_in[0];
    float* out = (float*)d_out;

    const int batch = in_sizes[0] / NC2;   // 32768
    triangle_kernel<<<batch, THREADS>>>(decompFE, out);
}

// round 7
// speedup vs baseline: 1.1183x; 1.0115x over previous
#include <cuda_runtime.h>
#include <cstdint>

// Triangle_39719857553609 — FINAL (R3 structure, best measured config).
//   in : decompFE [32768, 2016] f32 (flat strict-lower-triangle, tril(-1) order)
//   out: [32768, 64, 64] f32, symmetric, zero diagonal.
//
// One CTA per matrix, 256 threads, 24.4 KB smem (8 CTAs/SM):
//   cp.async.bulk G->S (8064 B row, mbarrier)
//   -> build 64x64 symmetric matrix in smem (4 float4/thread)
//   -> fence.proxy.async -> cp.async.bulk S->G (16 KB).
//
// Roofline: 264 MB read + 537 MB write, measured 6.5 TB/s (82% of HBM spec).
// Six structural variants (R1-R6) all plateau at 6.4-6.5 TB/s -> machine
// ceiling for this 1:2 R/W mix. This config had best DRAM% and ncu duration.

#define NC2        2016
#define ROW_BYTES  (NC2 * 4)            // 8064
#define N_ATOMS    64
#define MAT        (N_ATOMS * N_ATOMS)  // 4096
#define MAT_BYTES  (MAT * 4)            // 16384
#define THREADS    256

__device__ __forceinline__ uint32_t smem_u32(const void* p) {
    uint32_t a;
    asm("{ .reg .u64 t; cvta.to.shared.u64 t, %1; cvt.u32.u64 %0, t; }"
        : "=r"(a) : "l"(p));
    return a;
}

__global__ __launch_bounds__(THREADS) void triangle_kernel(
    const float* __restrict__ in, float* __restrict__ out)
{
    __shared__ alignas(16) float s_row[NC2];
    __shared__ alignas(16) float s_mat[MAT];
    __shared__ alignas(8)  uint64_t s_mbar;

    const int tid = threadIdx.x;
    const size_t b = blockIdx.x;

    const uint32_t mbar_a = smem_u32(&s_mbar);
    const uint32_t row_a  = smem_u32(s_row);
    const uint32_t mat_a  = smem_u32(s_mat);

    // ---- init mbarrier, single bulk load of the input row ----
    if (tid == 0) {
        asm volatile("mbarrier.init.shared.b64 [%0], 1;" :: "r"(mbar_a) : "memory");
        asm volatile("fence.proxy.async.shared::cta;" ::: "memory");
        asm volatile("mbarrier.arrive.expect_tx.shared.b64 _, [%0], %1;"
                     :: "r"(mbar_a), "r"((uint32_t)ROW_BYTES) : "memory");
        const float* src = in + b * NC2;
        asm volatile(
            "cp.async.bulk.shared::cta.global.mbarrier::complete_tx::bytes "
            "[%0], [%1], %2, [%3];"
            :: "r"(row_a), "l"(src), "r"((uint32_t)ROW_BYTES), "r"(mbar_a)
            : "memory");
    }
    __syncthreads();   // mbarrier init visible to all threads before wait

    // all threads wait for the row (parity 0)
    asm volatile(
        "{\n\t"
        ".reg .pred p;\n\t"
        "W_%=:\n\t"
        "mbarrier.try_wait.parity.shared.b64 p, [%0], 0;\n\t"
        "@!p bra W_%=;\n\t"
        "}"
        :: "r"(mbar_a) : "memory");

    // ---- build the full symmetric matrix in smem (4 float4 per thread) ----
    float4* m4 = reinterpret_cast<float4*>(s_mat);
    #pragma unroll
    for (int q = 0; q < MAT / 4 / THREADS; q++) {
        const int e4 = tid + q * THREADS;        // float4 index in matrix
        const int i  = e4 >> 4;                  // row (16 float4 per row)
        const int j0 = (e4 & 15) << 2;
        const int tri_i = (i * (i - 1)) >> 1;

        float4 v;
        float* vp = reinterpret_cast<float*>(&v);
        #pragma unroll
        for (int mI = 0; mI < 4; mI++) {
            const int j = j0 + mI;
            float val;
            if (j < i)       val = s_row[tri_i + j];                 // lower
            else if (j > i)  val = s_row[((j * (j - 1)) >> 1) + i];  // upper
            else             val = 0.0f;                             // diag
            vp[mI] = val;
        }
        m4[e4] = v;
    }
    __syncthreads();

    // ---- single 16 KB bulk store to GMEM ----
    if (tid == 0) {
        asm volatile("fence.proxy.async.shared::cta;" ::: "memory");
        float* dst = out + b * MAT;
        asm volatile(
            "cp.async.bulk.global.shared::cta.bulk_group [%0], [%1], %2;"
            :: "l"(dst), "r"(mat_a), "r"((uint32_t)MAT_BYTES)
            : "memory");
        asm volatile("cp.async.bulk.commit_group;" ::: "memory");
        asm volatile("cp.async.bulk.wait_group 0;" ::: "memory");
    }
}

extern "C" void kernel_launch(void* const* d_in, const int* in_sizes, int n_in,
                              void* d_out, int out_size)
{
    const float* decompFE = (const float*)d_in[0];
    float* out = (float*)d_out;

    const int batch = in_sizes[0] / NC2;   // 32768
    triangle_kernel<<<batch, THREADS>>>(decompFE, out);
}